// round 15
// baseline (speedup 1.0000x reference)
#include <cuda_runtime.h>
#include <cuda_bf16.h>
#include <cstdint>

// ---------------------------------------------------------------------------
// Problem constants: B=64, S=50, H=1024, E=16, K=2, AD=50, NH=5
// ---------------------------------------------------------------------------
#define TOK   3200
#define TOK2  6400
#define HD    1024
#define NEXP  16
#define NSLOT 13824
#define NTILE 216
#define OFF_R 65536

// ---------------- scratch ----------------
__device__ float g_x   [TOK2  * HD];
__device__ float g_h   [NSLOT * HD];
__device__ float g_eo  [NSLOT * HD];
__device__ int   g_cnt [NEXP];
__device__ int   g_run [NEXP];
__device__ int   g_off [NEXP + 1];
__device__ int   g_slot_token[NSLOT];
__device__ float g_slot_val  [NSLOT];
__device__ int   g_slot_of   [TOK2 * 2];
__device__ int   g_tile_expert[NTILE];
__device__ int   g_tidx[TOK2 * 2];
__device__ float g_tval[TOK2 * 2];
__device__ float g_c   [64 * 2048 * 50];      // [b][feature][s]
__device__ float g_c2  [TOK * 2048];
__device__ float g_fo  [TOK * HD];
__device__ float g_fo2 [TOK * HD];
__device__ float g_cmu [TOK];                 // cat-LN: sum -> mean
__device__ float g_crs [TOK];                 //         sumsq -> rstd
__device__ float g_bsum[TOK];
__device__ float g_bss [TOK];

__device__ __forceinline__ float gelu_f(float x) {
    return 0.5f * x * (1.0f + erff(x * 0.70710678118654752440f));
}

__device__ __forceinline__ uint32_t cvt_tf32(float x) {
    uint32_t r;
    asm("cvt.rna.tf32.f32 %0, %1;" : "=r"(r) : "f"(x));
    return r;
}

__device__ __forceinline__ void mma_tf32(float* c, const uint32_t* a, const uint32_t* b) {
    asm volatile(
        "mma.sync.aligned.m16n8k8.row.col.f32.tf32.tf32.f32 "
        "{%0,%1,%2,%3}, {%4,%5,%6,%7}, {%8,%9}, {%0,%1,%2,%3};"
        : "+f"(c[0]), "+f"(c[1]), "+f"(c[2]), "+f"(c[3])
        : "r"(a[0]), "r"(a[1]), "r"(a[2]), "r"(a[3]), "r"(b[0]), "r"(b[1]));
}

// ---------------- LayerNorm + gelu (float4), one block per row --------------
__global__ __launch_bounds__(256) void ln_gelu_kernel(
    const float* __restrict__ in, const float* __restrict__ g,
    const float* __restrict__ b, float* __restrict__ out, int width)
{
    long row = blockIdx.x;
    const float4* x4 = (const float4*)(in + row * width);
    const int w4 = width >> 2;
    float s = 0.f, ss = 0.f;
    for (int i = threadIdx.x; i < w4; i += 256) {
        float4 v = x4[i];
        s += v.x + v.y + v.z + v.w;
        ss = fmaf(v.x, v.x, fmaf(v.y, v.y, fmaf(v.z, v.z, fmaf(v.w, v.w, ss))));
    }
    __shared__ float sh1[256], sh2[256];
    sh1[threadIdx.x] = s; sh2[threadIdx.x] = ss;
    __syncthreads();
    for (int o = 128; o > 0; o >>= 1) {
        if (threadIdx.x < o) { sh1[threadIdx.x] += sh1[threadIdx.x + o];
                               sh2[threadIdx.x] += sh2[threadIdx.x + o]; }
        __syncthreads();
    }
    float mean = sh1[0] / width;
    float rstd = rsqrtf(sh2[0] / width - mean * mean + 1e-5f);
    const float4* g4 = (const float4*)g;
    const float4* b4 = (const float4*)b;
    float4* o4 = (float4*)(out + row * width);
    for (int i = threadIdx.x; i < w4; i += 256) {
        float4 v = x4[i], gg = g4[i], bb = b4[i];
        float4 r;
        r.x = gelu_f((v.x - mean) * rstd * gg.x + bb.x);
        r.y = gelu_f((v.y - mean) * rstd * gg.y + bb.y);
        r.z = gelu_f((v.z - mean) * rstd * gg.z + bb.z);
        r.w = gelu_f((v.w - mean) * rstd * gg.w + bb.w);
        o4[i] = r;
    }
}

// ---------------- routing init (also zeroes LN accumulators) ----------------
__global__ void init_routing() {
    int i = blockIdx.x * blockDim.x + threadIdx.x;
    if (i < NEXP)  { g_cnt[i] = 0; g_run[i] = 0; }
    if (i < NTILE) g_tile_expert[i] = -1;
    if (i < NSLOT) { g_slot_token[i] = -1; g_slot_val[i] = 0.f; }
    if (i < TOK)   { g_bsum[i] = 0.f; g_bss[i] = 0.f; g_cmu[i] = 0.f; g_crs[i] = 0.f; }
}

// ---------------- gating (float4 row reads) ----------------
__global__ __launch_bounds__(256) void gate_topk2(
    const float* __restrict__ gw, const float* __restrict__ gb)
{
    extern __shared__ float sgw[];   // [1024][17]
    __shared__ float sgb[NEXP];
    const int tid = threadIdx.x;
    for (int i = tid; i < HD * NEXP; i += 256) {
        int h = i >> 4, e = i & 15;
        sgw[h * 17 + e] = gw[i];
    }
    if (tid < NEXP) sgb[tid] = gb[tid];
    __syncthreads();

    const int warp = tid >> 5, lane = tid & 31;
    for (int tt = 0; tt < 4; tt++) {
        int t = blockIdx.x * 32 + warp * 4 + tt;
        const float4* xr4 = (const float4*)(g_x + (long)t * HD);
        float acc[NEXP];
#pragma unroll
        for (int e = 0; e < NEXP; e++) acc[e] = 0.f;
        for (int i = lane; i < 256; i += 32) {
            float4 xv = xr4[i];
            int h = i << 2;
            const float* s0 = &sgw[(h + 0) * 17];
            const float* s1 = &sgw[(h + 1) * 17];
            const float* s2 = &sgw[(h + 2) * 17];
            const float* s3 = &sgw[(h + 3) * 17];
#pragma unroll
            for (int e = 0; e < NEXP; e++)
                acc[e] = fmaf(xv.x, s0[e], fmaf(xv.y, s1[e],
                         fmaf(xv.z, s2[e], fmaf(xv.w, s3[e], acc[e]))));
        }
#pragma unroll
        for (int e = 0; e < NEXP; e++) {
#pragma unroll
            for (int o = 16; o > 0; o >>= 1)
                acc[e] += __shfl_xor_sync(0xffffffffu, acc[e], o);
        }
        if (lane == 0) {
            float mx = acc[0] + sgb[0];
            float lg[NEXP];
#pragma unroll
            for (int e = 0; e < NEXP; e++) { lg[e] = acc[e] + sgb[e]; mx = fmaxf(mx, lg[e]); }
            float p[NEXP]; float sum = 0.f;
#pragma unroll
            for (int e = 0; e < NEXP; e++) { p[e] = expf(lg[e] - mx); sum += p[e]; }
            float inv = 1.f / sum;
            int i0 = 0; float v0 = -1.f;
#pragma unroll
            for (int e = 0; e < NEXP; e++) if (p[e] > v0) { v0 = p[e]; i0 = e; }
            int i1 = 0; float v1 = -1.f;
#pragma unroll
            for (int e = 0; e < NEXP; e++) if (e != i0 && p[e] > v1) { v1 = p[e]; i1 = e; }
            g_tidx[2 * t]     = i0; g_tval[2 * t]     = v0 * inv;
            g_tidx[2 * t + 1] = i1; g_tval[2 * t + 1] = v1 * inv;
            atomicAdd(&g_cnt[i0], 1);
            atomicAdd(&g_cnt[i1], 1);
        }
    }
}

__global__ void prefix_kernel() {
    if (threadIdx.x == 0 && blockIdx.x == 0) {
        int off = 0;
        for (int e = 0; e < NEXP; e++) {
            g_off[e] = off;
            int tiles = (g_cnt[e] + 63) >> 6;
            for (int tt = 0; tt < tiles; tt++) g_tile_expert[(off >> 6) + tt] = e;
            off += tiles << 6;
        }
        g_off[NEXP] = off;
    }
}

__global__ void scatter_kernel() {
    int t = blockIdx.x * blockDim.x + threadIdx.x;
    if (t >= TOK2) return;
    for (int k = 0; k < 2; k++) {
        int e = g_tidx[2 * t + k];
        int pos = atomicAdd(&g_run[e], 1);
        int slot = g_off[e] + pos;
        g_slot_token[slot] = t;
        g_slot_val[slot]   = g_tval[2 * t + k];
        g_slot_of[2 * t + k] = slot;
    }
}

// ===========================================================================
// tf32 tensor-core GEMM (64x128 tile, 256 threads, cp.async double buffer)
// ===========================================================================
#define AS_STRIDE 20
#define BS_STRIDE 136

__global__ __launch_bounds__(256) void gemm_tc(
    const float* __restrict__ A, int lda, int K,
    const float* __restrict__ W, long estride,
    const float* __restrict__ bias, int bstride,
    float* __restrict__ out,
    const int*   __restrict__ slot_token,
    const float* __restrict__ slot_val,
    const int*   __restrict__ tile_expert,
    int do_gelu, int use_val)
{
    int e = tile_expert ? tile_expert[blockIdx.x] : 0;
    if (e < 0) return;
    const int m0 = blockIdx.x * 64;
    const int n0 = blockIdx.y * 128;
    const float* We = W + (long)e * estride + n0;
    const float* be = bias + (long)e * bstride + n0;

    __shared__ float As[2][64 * AS_STRIDE];
    __shared__ float Bs[2][16 * BS_STRIDE];

    const int tid  = threadIdx.x;
    const int warp = tid >> 5, lane = tid & 31;
    const int wm = warp >> 2;
    const int wn = warp & 3;
    const int gid = lane >> 2;
    const int qid = lane & 3;

    const int a_row = tid >> 2;
    const int a_kq  = (tid & 3) << 2;
    long arow;
    {
        int tok = slot_token ? slot_token[m0 + a_row] : (m0 + a_row);
        if (tok < 0) tok = 0;
        arow = (long)tok * lda;
    }

    float c[2][4][4];
#pragma unroll
    for (int mt = 0; mt < 2; mt++)
#pragma unroll
        for (int nt = 0; nt < 4; nt++)
#pragma unroll
            for (int r = 0; r < 4; r++) c[mt][nt][r] = 0.f;

    const int NKC = K >> 4;

#define ISSUE_STAGE(K0, S)                                                        \
    {                                                                             \
        uint32_t da = (uint32_t)__cvta_generic_to_shared(                         \
            &As[S][a_row * AS_STRIDE + a_kq]);                                    \
        asm volatile("cp.async.cg.shared.global [%0], [%1], 16;" ::               \
                     "r"(da), "l"(A + arow + (K0) + a_kq));                       \
        _Pragma("unroll")                                                         \
        for (int j = 0; j < 2; j++) {                                             \
            int ch = tid + j * 256;                                               \
            int krow = ch >> 5, nq = (ch & 31) << 2;                              \
            uint32_t db = (uint32_t)__cvta_generic_to_shared(                     \
                &Bs[S][krow * BS_STRIDE + nq]);                                   \
            asm volatile("cp.async.cg.shared.global [%0], [%1], 16;" ::           \
                         "r"(db), "l"(We + (long)((K0) + krow) * 1024 + nq));     \
        }                                                                         \
        asm volatile("cp.async.commit_group;");                                   \
    }

    ISSUE_STAGE(0, 0);
    int s = 0;
    for (int kc = 0; kc < NKC; kc++) {
        if (kc + 1 < NKC) {
            ISSUE_STAGE((kc + 1) << 4, s ^ 1);
            asm volatile("cp.async.wait_group 1;");
        } else {
            asm volatile("cp.async.wait_group 0;");
        }
        __syncthreads();

#pragma unroll
        for (int kb = 0; kb < 2; kb++) {
            uint32_t af[2][4], bf[4][2];
            const float* ap = &As[s][0];
            const float* bp = &Bs[s][0];
#pragma unroll
            for (int mt = 0; mt < 2; mt++) {
                int r = wm * 32 + mt * 16 + gid;
                af[mt][0] = cvt_tf32(ap[(r)     * AS_STRIDE + kb * 8 + qid]);
                af[mt][1] = cvt_tf32(ap[(r + 8) * AS_STRIDE + kb * 8 + qid]);
                af[mt][2] = cvt_tf32(ap[(r)     * AS_STRIDE + kb * 8 + qid + 4]);
                af[mt][3] = cvt_tf32(ap[(r + 8) * AS_STRIDE + kb * 8 + qid + 4]);
            }
#pragma unroll
            for (int nt = 0; nt < 4; nt++) {
                int n = wn * 32 + nt * 8 + gid;
                bf[nt][0] = cvt_tf32(bp[(kb * 8 + qid)     * BS_STRIDE + n]);
                bf[nt][1] = cvt_tf32(bp[(kb * 8 + qid + 4) * BS_STRIDE + n]);
            }
#pragma unroll
            for (int mt = 0; mt < 2; mt++)
#pragma unroll
                for (int nt = 0; nt < 4; nt++)
                    mma_tf32(c[mt][nt], af[mt], bf[nt]);
        }
        __syncthreads();
        s ^= 1;
    }

#pragma unroll
    for (int mt = 0; mt < 2; mt++) {
        int rbase = m0 + wm * 32 + mt * 16 + gid;
#pragma unroll
        for (int half = 0; half < 2; half++) {
            int r = rbase + half * 8;
            float sv = use_val ? slot_val[r] : 1.f;
#pragma unroll
            for (int nt = 0; nt < 4; nt++) {
                int colb = wn * 32 + nt * 8 + qid * 2;
                float v0 = c[mt][nt][half * 2 + 0] + be[colb];
                float v1 = c[mt][nt][half * 2 + 1] + be[colb + 1];
                if (do_gelu) { v0 = gelu_f(v0); v1 = gelu_f(v1); }
                if (use_val) { v0 *= sv; v1 *= sv; }
                *(float2*)(out + (long)r * 1024 + n0 + colb) = make_float2(v0, v1);
            }
        }
    }
#undef ISSUE_STAGE
}

// ---- combine 2 expert outputs + LN + gelu, fused cat-LN stat accumulation --
__global__ __launch_bounds__(256) void moe_combine_ln(
    const float* __restrict__ g0, const float* __restrict__ b0,
    const float* __restrict__ g1, const float* __restrict__ b1,
    float* __restrict__ dout)
{
    int t = blockIdx.x;
    const float4* r0 = (const float4*)(g_eo + (long)g_slot_of[2 * t] * HD);
    const float4* r1 = (const float4*)(g_eo + (long)g_slot_of[2 * t + 1] * HD);
    const float4* G  = (const float4*)((t < TOK) ? g0 : g1);
    const float4* Bv = (const float4*)((t < TOK) ? b0 : b1);
    float s = 0.f, ss = 0.f;
    {
        int i = threadIdx.x;
        float4 a = r0[i], b = r1[i];
        float vx = a.x + b.x, vy = a.y + b.y, vz = a.z + b.z, vw = a.w + b.w;
        s += vx + vy + vz + vw;
        ss = fmaf(vx, vx, fmaf(vy, vy, fmaf(vz, vz, fmaf(vw, vw, ss))));
    }
    __shared__ float sh1[256], sh2[256];
    sh1[threadIdx.x] = s; sh2[threadIdx.x] = ss;
    __syncthreads();
    for (int o = 128; o > 0; o >>= 1) {
        if (threadIdx.x < o) { sh1[threadIdx.x] += sh1[threadIdx.x + o];
                               sh2[threadIdx.x] += sh2[threadIdx.x + o]; }
        __syncthreads();
    }
    float mean = sh1[0] / HD;
    float rstd = rsqrtf(sh2[0] / HD - mean * mean + 1e-5f);
    float4* orow = (float4*)(dout + OFF_R + (long)t * HD);
    float os, oss;
    {
        int i = threadIdx.x;
        float4 a = r0[i], b = r1[i], gg = G[i], bb = Bv[i];
        float4 r;
        r.x = gelu_f(((a.x + b.x) - mean) * rstd * gg.x + bb.x);
        r.y = gelu_f(((a.y + b.y) - mean) * rstd * gg.y + bb.y);
        r.z = gelu_f(((a.z + b.z) - mean) * rstd * gg.z + bb.z);
        r.w = gelu_f(((a.w + b.w) - mean) * rstd * gg.w + bb.w);
        orow[i] = r;
        os  = r.x + r.y + r.z + r.w;
        oss = fmaf(r.x, r.x, fmaf(r.y, r.y, fmaf(r.z, r.z, r.w * r.w)));
    }
    // second reduction: accumulate cat-LN stats for row (t mod TOK)
    __syncthreads();
    sh1[threadIdx.x] = os; sh2[threadIdx.x] = oss;
    __syncthreads();
    for (int o = 128; o > 0; o >>= 1) {
        if (threadIdx.x < o) { sh1[threadIdx.x] += sh1[threadIdx.x + o];
                               sh2[threadIdx.x] += sh2[threadIdx.x + o]; }
        __syncthreads();
    }
    if (threadIdx.x == 0) {
        int tt = (t < TOK) ? t : t - TOK;
        atomicAdd(&g_cmu[tt], sh1[0]);
        atomicAdd(&g_crs[tt], sh2[0]);
    }
}

// -------- finalize cat-LN stats: sums -> mean/rstd --------------------------
__global__ void cat_mu_kernel() {
    int t = blockIdx.x * blockDim.x + threadIdx.x;
    if (t >= TOK) return;
    float mean = g_cmu[t] / 2048.f;
    float rs = rsqrtf(g_crs[t] / 2048.f - mean * mean + 1e-5f);
    g_cmu[t] = mean;
    g_crs[t] = rs;
}

// -------- cat-LN apply + transpose into g_c[b][f][s] ------------------------
__global__ __launch_bounds__(256) void cat_tr_kernel(
    const float* __restrict__ dout,
    const float* __restrict__ g2, const float* __restrict__ b2)
{
    __shared__ float sT[64 * 52];
    const int b  = blockIdx.x;
    const int f0 = blockIdx.y * 64;
    const int tid = threadIdx.x;
    for (int i = tid; i < 3200; i += 256) {
        int s2 = i >> 6, fl = i & 63;
        int f = f0 + fl, t = b * 50 + s2;
        float v = (f < HD) ? dout[OFF_R + (long)t * HD + f]
                           : dout[OFF_R + (long)(TOK + t) * HD + (f - HD)];
        v = (v - g_cmu[t]) * g_crs[t] * g2[f] + b2[f];
        sT[fl * 52 + s2] = gelu_f(v);
    }
    __syncthreads();
    for (int i = tid; i < 3200; i += 256) {
        int fl = i / 50, s2 = i % 50;
        g_c[((long)b * 2048 + f0 + fl) * 50 + s2] = sT[fl * 52 + s2];
    }
}

// ===========================================================================
// Fused attention layer, 320 threads; balanced 2x5 tiles; __expf softmax.
// ===========================================================================
#define ATT_OX 0
#define ATT_OQ 3328
#define ATT_OA 13056
#define ATT_OW 16384
#define ATT_OB 24184
#define ATT_SMEM_FLOATS 24448
#define ATT_THREADS 320

__global__ __launch_bounds__(ATT_THREADS, 1) void attn_layer_fused(
    const float* __restrict__ wi, const float* __restrict__ bi,
    const float* __restrict__ wo, const float* __restrict__ bo,
    const float* __restrict__ wp, const float* __restrict__ bp)
{
    extern __shared__ float sm[];
    float* sX  = sm + ATT_OX;    // [64][52]
    float* sQ  = sm + ATT_OQ;    // [64][152] qkv; later reused as sM [64][52]
    float* sA  = sm + ATT_OA;    // [64][52]
    float* sW  = sm + ATT_OW;    // [150][52]
    float* sbi = sm + ATT_OB;    // [150]
    float* sbo = sbi + 150;      // [50]
    float* sbp = sbo + 50;       // [50]

    const int n = blockIdx.x;
    const int tid = threadIdx.x;

    // phase 1: load x rows + wi + bi
    for (int i = tid; i < 3200; i += ATT_THREADS) {
        int m = i / 50, k = i % 50;
        sX[m * 52 + k] = g_c[((long)m * 2048 + n) * 50 + k];
    }
    for (int i = tid; i < 7500; i += ATT_THREADS)
        sW[(i / 50) * 52 + (i % 50)] = wi[i];
    if (tid < 150) sbi[tid] = bi[tid];
    __syncthreads();

    // phase 2: qkv = x @ wi^T + bi  (960 tasks of 2x5 -> 3 even passes)
    for (int t = tid; t < 960; t += ATT_THREADS) {
        int tm = (t / 30) * 2, tf = (t % 30) * 5;
        float acc[2][5];
#pragma unroll
        for (int i = 0; i < 2; i++)
#pragma unroll
            for (int j = 0; j < 5; j++) acc[i][j] = sbi[tf + j];
#pragma unroll 5
        for (int k = 0; k < 50; k++) {
            float a0 = sX[(tm) * 52 + k], a1 = sX[(tm + 1) * 52 + k];
#pragma unroll
            for (int j = 0; j < 5; j++) {
                float w = sW[(tf + j) * 52 + k];
                acc[0][j] = fmaf(a0, w, acc[0][j]);
                acc[1][j] = fmaf(a1, w, acc[1][j]);
            }
        }
#pragma unroll
        for (int i = 0; i < 2; i++)
#pragma unroll
            for (int j = 0; j < 5; j++)
                sQ[(tm + i) * 152 + tf + j] = acc[i][j];
    }
    __syncthreads();

    // phase 3: attention, one task per thread (320 = 64 l x 5 h)
    {
        const float scale = 0.31622776601683794f;
        int l = tid & 63, h = tid >> 6;
        const float* qp = &sQ[l * 152 + h * 10];
        float q[10];
#pragma unroll
        for (int d = 0; d < 10; d++) q[d] = qp[d];
        float sc[64];
        float mx = -1e30f;
#pragma unroll
        for (int m = 0; m < 64; m++) {
            const float* kp = &sQ[m * 152 + 50 + h * 10];
            float s = 0.f;
#pragma unroll
            for (int d = 0; d < 10; d++) s = fmaf(q[d], kp[d], s);
            s *= scale;
            sc[m] = s;
            mx = fmaxf(mx, s);
        }
        float sum = 0.f;
#pragma unroll
        for (int m = 0; m < 64; m++) { sc[m] = __expf(sc[m] - mx); sum += sc[m]; }
        float o[10];
#pragma unroll
        for (int d = 0; d < 10; d++) o[d] = 0.f;
#pragma unroll
        for (int m = 0; m < 64; m++) {
            const float* vp = &sQ[m * 152 + 100 + h * 10];
            float ev = sc[m];
#pragma unroll
            for (int d = 0; d < 10; d++) o[d] = fmaf(ev, vp[d], o[d]);
        }
        float inv = 1.f / sum;
        float* ap = &sA[l * 52 + h * 10];
#pragma unroll
        for (int d = 0; d < 10; d++) ap[d] = o[d] * inv;
    }
    for (int i = tid; i < 2500; i += ATT_THREADS)
        sW[(i / 50) * 52 + (i % 50)] = wo[i];
    for (int i = tid; i < 2500; i += ATT_THREADS)
        sW[(50 + i / 50) * 52 + (i % 50)] = wp[i];
    if (tid < 50) { sbo[tid] = bo[tid]; sbp[tid] = bp[tid]; }
    __syncthreads();

    // phase 4: sM = gelu(att @ wo^T + bo) -> sQ ([64][52]); 320 tasks of 2x5
    for (int t = tid; t < 320; t += ATT_THREADS) {
        int tm = (t / 10) * 2, tf = (t % 10) * 5;
        float acc[2][5];
#pragma unroll
        for (int i = 0; i < 2; i++)
#pragma unroll
            for (int j = 0; j < 5; j++) acc[i][j] = sbo[tf + j];
#pragma unroll 5
        for (int k = 0; k < 50; k++) {
            float a0 = sA[(tm) * 52 + k], a1 = sA[(tm + 1) * 52 + k];
#pragma unroll
            for (int j = 0; j < 5; j++) {
                float w = sW[(tf + j) * 52 + k];
                acc[0][j] = fmaf(a0, w, acc[0][j]);
                acc[1][j] = fmaf(a1, w, acc[1][j]);
            }
        }
#pragma unroll
        for (int i = 0; i < 2; i++)
#pragma unroll
            for (int j = 0; j < 5; j++)
                sQ[(tm + i) * 52 + tf + j] = gelu_f(acc[i][j]);
    }
    __syncthreads();

    // phase 5: c = x + gelu(sM @ wp^T + bp); 320 tasks of 2x5
    for (int t = tid; t < 320; t += ATT_THREADS) {
        int tm = (t / 10) * 2, tf = (t % 10) * 5;
        float acc[2][5];
#pragma unroll
        for (int i = 0; i < 2; i++)
#pragma unroll
            for (int j = 0; j < 5; j++) acc[i][j] = sbp[tf + j];
#pragma unroll 5
        for (int k = 0; k < 50; k++) {
            float a0 = sQ[(tm) * 52 + k], a1 = sQ[(tm + 1) * 52 + k];
#pragma unroll
            for (int j = 0; j < 5; j++) {
                float w = sW[(50 + tf + j) * 52 + k];
                acc[0][j] = fmaf(a0, w, acc[0][j]);
                acc[1][j] = fmaf(a1, w, acc[1][j]);
            }
        }
#pragma unroll
        for (int i = 0; i < 2; i++)
#pragma unroll
            for (int j = 0; j < 5; j++) {
                int m = tm + i, f = tf + j;
                g_c[((long)m * 2048 + n) * 50 + f] =
                    sX[m * 52 + f] + gelu_f(acc[i][j]);
            }
    }
}

// -------- back-LN stats ------------------------------------------------------
__global__ __launch_bounds__(256) void back_stats_kernel()
{
    __shared__ float sT[64 * 52];
    const int b  = blockIdx.x;
    const int f0 = blockIdx.y * 64;
    const int tid = threadIdx.x;
    for (int i = tid; i < 3200; i += 256) {
        int fl = i / 50, s2 = i % 50;
        sT[fl * 52 + s2] = g_c[((long)b * 2048 + f0 + fl) * 50 + s2];
    }
    __syncthreads();
    if (tid < 200) {
        int s2 = tid % 50, part = tid / 50;
        float s = 0.f, ss = 0.f;
        for (int fl = part * 16; fl < part * 16 + 16; fl++) {
            float v = sT[fl * 52 + s2];
            s += v; ss = fmaf(v, v, ss);
        }
        atomicAdd(&g_bsum[b * 50 + s2], s);
        atomicAdd(&g_bss [b * 50 + s2], ss);
    }
}

__global__ void back_mu_kernel() {
    int t = blockIdx.x * blockDim.x + threadIdx.x;
    if (t >= TOK) return;
    float mean = g_bsum[t] / 2048.f;
    float rs = rsqrtf(g_bss[t] / 2048.f - mean * mean + 1e-5f);
    g_bsum[t] = mean;
    g_bss[t]  = rs;
}

// -------- back-LN apply + transpose into g_c2 -------------------------------
__global__ __launch_bounds__(256) void back_tr_kernel(
    const float* __restrict__ aag, const float* __restrict__ aab)
{
    __shared__ float sT[64 * 52];
    const int b  = blockIdx.x;
    const int f0 = blockIdx.y * 64;
    const int tid = threadIdx.x;
    for (int i = tid; i < 3200; i += 256) {
        int fl = i / 50, s2 = i % 50;
        sT[fl * 52 + s2] = g_c[((long)b * 2048 + f0 + fl) * 50 + s2];
    }
    __syncthreads();
    for (int i = tid; i < 3200; i += 256) {
        int s2 = i >> 6, fl = i & 63;
        int t = b * 50 + s2, f = f0 + fl;
        float v = (sT[fl * 52 + s2] - g_bsum[t]) * g_bss[t] * aag[f] + aab[f];
        g_c2[(long)t * 2048 + f] = gelu_f(v);
    }
}

// ---------------- mean over S -> result ----------------
__global__ __launch_bounds__(256) void mean_kernel(float* __restrict__ dout)
{
    int bb = blockIdx.x;
    for (int hh = threadIdx.x; hh < HD; hh += 256) {
        float s = 0.f;
        for (int s2 = 0; s2 < 50; s2++)
            s += g_fo2[((long)bb * 50 + s2) * HD + hh];
        dout[bb * HD + hh] = s * (1.0f / 50.0f);
    }
}

// ---------------------------------------------------------------------------
extern "C" void kernel_launch(void* const* d_in, const int* in_sizes, int n_in,
                              void* d_out, int out_size)
{
    const float* cls_x   = (const float*)d_in[0];
    const float* cls_x1  = (const float*)d_in[1];
    const float* ln_g    = (const float*)d_in[2];
    const float* ln_b    = (const float*)d_in[3];
    const float* ln1_g   = (const float*)d_in[4];
    const float* ln1_b   = (const float*)d_in[5];
    const float* gate_w  = (const float*)d_in[6];
    const float* gate_b  = (const float*)d_in[7];
    const float* W1      = (const float*)d_in[8];
    const float* b1      = (const float*)d_in[9];
    const float* W2      = (const float*)d_in[10];
    const float* b2      = (const float*)d_in[11];
    const float* lnout_g = (const float*)d_in[12];
    const float* lnout_b = (const float*)d_in[13];
    const float* lnout1_g= (const float*)d_in[14];
    const float* lnout1_b= (const float*)d_in[15];
    const float* ln2_g   = (const float*)d_in[16];
    const float* ln2_b   = (const float*)d_in[17];
    const float* attn_in_w  = (const float*)d_in[18];
    const float* attn_in_b  = (const float*)d_in[19];
    const float* attn_out_w = (const float*)d_in[20];
    const float* attn_out_b = (const float*)d_in[21];
    const float* post_w  = (const float*)d_in[22];
    const float* post_b  = (const float*)d_in[23];
    const float* aa_g    = (const float*)d_in[24];
    const float* aa_b    = (const float*)d_in[25];
    const float* fus_w   = (const float*)d_in[26];
    const float* fus_b   = (const float*)d_in[27];
    const float* ln3_g   = (const float*)d_in[28];
    const float* ln3_b   = (const float*)d_in[29];
    float* out = (float*)d_out;

    float *p_x, *p_h, *p_eo, *p_c2, *p_fo, *p_fo2;
    int *p_slot_token, *p_tile_expert; float *p_slot_val;
    cudaGetSymbolAddress((void**)&p_x,   g_x);
    cudaGetSymbolAddress((void**)&p_h,   g_h);
    cudaGetSymbolAddress((void**)&p_eo,  g_eo);
    cudaGetSymbolAddress((void**)&p_c2,  g_c2);
    cudaGetSymbolAddress((void**)&p_fo,  g_fo);
    cudaGetSymbolAddress((void**)&p_fo2, g_fo2);
    cudaGetSymbolAddress((void**)&p_slot_token,  g_slot_token);
    cudaGetSymbolAddress((void**)&p_slot_val,    g_slot_val);
    cudaGetSymbolAddress((void**)&p_tile_expert, g_tile_expert);

    const int SGW_BYTES = HD * 17 * 4;                 // 69632
    const int ATT_BYTES = ATT_SMEM_FLOATS * 4;         // 97792
    cudaFuncSetAttribute(gate_topk2, cudaFuncAttributeMaxDynamicSharedMemorySize,
                         SGW_BYTES);
    cudaFuncSetAttribute(attn_layer_fused, cudaFuncAttributeMaxDynamicSharedMemorySize,
                         ATT_BYTES);

    // Stage A
    ln_gelu_kernel<<<TOK, 256>>>(cls_x,  ln_g,  ln_b,  p_x,             HD);
    ln_gelu_kernel<<<TOK, 256>>>(cls_x1, ln1_g, ln1_b, p_x + TOK * HD,  HD);

    // Stage B
    init_routing<<<54, 256>>>();
    gate_topk2<<<TOK2 / 32, 256, SGW_BYTES>>>(gate_w, gate_b);
    prefix_kernel<<<1, 32>>>();
    scatter_kernel<<<(TOK2 + 255) / 256, 256>>>();

    // Stage C
    gemm_tc<<<dim3(NTILE, 8), 256>>>(p_x, HD, HD, W1, 1024L * 1024, b1, 1024,
                                     p_h, p_slot_token, nullptr, p_tile_expert, 1, 0);
    gemm_tc<<<dim3(NTILE, 8), 256>>>(p_h, HD, HD, W2, 1024L * 1024, b2, 1024,
                                     p_eo, nullptr, p_slot_val, p_tile_expert, 1, 1);

    // Stage D (also accumulates cat-LN stats)
    moe_combine_ln<<<TOK2, 256>>>(lnout_g, lnout_b, lnout1_g, lnout1_b, out);

    // Stage E
    cat_mu_kernel<<<(TOK + 255) / 256, 256>>>();
    cat_tr_kernel<<<dim3(64, 32), 256>>>(out, ln2_g, ln2_b);

    // Stage F
    for (int i = 0; i < 4; i++) {
        attn_layer_fused<<<2048, ATT_THREADS, ATT_BYTES>>>(
            attn_in_w + i * 7500, attn_in_b + i * 150,
            attn_out_w + i * 2500, attn_out_b + i * 50,
            post_w + i * 2500, post_b + i * 50);
    }

    // Stage G
    back_stats_kernel<<<dim3(64, 32), 256>>>();
    back_mu_kernel<<<(TOK + 255) / 256, 256>>>();
    back_tr_kernel<<<dim3(64, 32), 256>>>(aa_g, aa_b);

    // Stage H
    gemm_tc<<<dim3(TOK / 64, 8), 256>>>(p_c2, 2048, 2048, fus_w, 0, fus_b, 0,
                                        p_fo, nullptr, nullptr, nullptr, 0, 0);

    // Stage I
    ln_gelu_kernel<<<TOK, 256>>>(p_fo, ln3_g, ln3_b, p_fo2, HD);
    mean_kernel<<<64, 256>>>(out);
}

// round 17
// speedup vs baseline: 1.1945x; 1.1945x over previous
#include <cuda_runtime.h>
#include <cuda_bf16.h>
#include <cstdint>

// ---------------------------------------------------------------------------
// Problem constants: B=64, S=50, H=1024, E=16, K=2, AD=50, NH=5
// ---------------------------------------------------------------------------
#define TOK   3200
#define TOK2  6400
#define HD    1024
#define NEXP  16
#define NSLOT 13824
#define NTILE 216
#define OFF_R 65536

// ---------------- scratch ----------------
__device__ float g_x   [TOK2  * HD];
__device__ float g_h   [NSLOT * HD];
__device__ float g_eo  [NSLOT * HD];
__device__ int   g_cnt [NEXP];
__device__ int   g_run [NEXP];
__device__ int   g_off [NEXP + 1];
__device__ int   g_slot_token[NSLOT];
__device__ float g_slot_val  [NSLOT];
__device__ int   g_slot_of   [TOK2 * 2];
__device__ int   g_tile_expert[NTILE];
__device__ int   g_tidx[TOK2 * 2];
__device__ float g_tval[TOK2 * 2];
__device__ float g_c   [64 * 2048 * 50];      // [b][feature][s]
__device__ float g_c2  [TOK * 2048];
__device__ float g_fo  [TOK * HD];
__device__ float g_fo2 [TOK * HD];
__device__ float g_cmu [TOK];                 // cat-LN: sum -> mean
__device__ float g_crs [TOK];                 //         sumsq -> rstd
__device__ float g_bsum[TOK];
__device__ float g_bss [TOK];

__device__ __forceinline__ float gelu_f(float x) {
    return 0.5f * x * (1.0f + erff(x * 0.70710678118654752440f));
}

__device__ __forceinline__ uint32_t cvt_tf32(float x) {
    uint32_t r;
    asm("cvt.rna.tf32.f32 %0, %1;" : "=r"(r) : "f"(x));
    return r;
}

__device__ __forceinline__ void mma_tf32(float* c, const uint32_t* a, const uint32_t* b) {
    asm volatile(
        "mma.sync.aligned.m16n8k8.row.col.f32.tf32.tf32.f32 "
        "{%0,%1,%2,%3}, {%4,%5,%6,%7}, {%8,%9}, {%0,%1,%2,%3};"
        : "+f"(c[0]), "+f"(c[1]), "+f"(c[2]), "+f"(c[3])
        : "r"(a[0]), "r"(a[1]), "r"(a[2]), "r"(a[3]), "r"(b[0]), "r"(b[1]));
}

// ---------------- LayerNorm + gelu (float4), one block per row --------------
__global__ __launch_bounds__(256) void ln_gelu_kernel(
    const float* __restrict__ in, const float* __restrict__ g,
    const float* __restrict__ b, float* __restrict__ out, int width)
{
    long row = blockIdx.x;
    const float4* x4 = (const float4*)(in + row * width);
    const int w4 = width >> 2;
    float s = 0.f, ss = 0.f;
    for (int i = threadIdx.x; i < w4; i += 256) {
        float4 v = x4[i];
        s += v.x + v.y + v.z + v.w;
        ss = fmaf(v.x, v.x, fmaf(v.y, v.y, fmaf(v.z, v.z, fmaf(v.w, v.w, ss))));
    }
    __shared__ float sh1[256], sh2[256];
    sh1[threadIdx.x] = s; sh2[threadIdx.x] = ss;
    __syncthreads();
    for (int o = 128; o > 0; o >>= 1) {
        if (threadIdx.x < o) { sh1[threadIdx.x] += sh1[threadIdx.x + o];
                               sh2[threadIdx.x] += sh2[threadIdx.x + o]; }
        __syncthreads();
    }
    float mean = sh1[0] / width;
    float rstd = rsqrtf(sh2[0] / width - mean * mean + 1e-5f);
    const float4* g4 = (const float4*)g;
    const float4* b4 = (const float4*)b;
    float4* o4 = (float4*)(out + row * width);
    for (int i = threadIdx.x; i < w4; i += 256) {
        float4 v = x4[i], gg = g4[i], bb = b4[i];
        float4 r;
        r.x = gelu_f((v.x - mean) * rstd * gg.x + bb.x);
        r.y = gelu_f((v.y - mean) * rstd * gg.y + bb.y);
        r.z = gelu_f((v.z - mean) * rstd * gg.z + bb.z);
        r.w = gelu_f((v.w - mean) * rstd * gg.w + bb.w);
        o4[i] = r;
    }
}

// ---------------- routing init (also zeroes LN accumulators) ----------------
__global__ void init_routing() {
    int i = blockIdx.x * blockDim.x + threadIdx.x;
    if (i < NEXP)  { g_cnt[i] = 0; g_run[i] = 0; }
    if (i < NTILE) g_tile_expert[i] = -1;
    if (i < NSLOT) { g_slot_token[i] = -1; g_slot_val[i] = 0.f; }
    if (i < TOK)   { g_bsum[i] = 0.f; g_bss[i] = 0.f; g_cmu[i] = 0.f; g_crs[i] = 0.f; }
}

// ---------------- gating (float4 row reads) ----------------
__global__ __launch_bounds__(256) void gate_topk2(
    const float* __restrict__ gw, const float* __restrict__ gb)
{
    extern __shared__ float sgw[];   // [1024][17]
    __shared__ float sgb[NEXP];
    const int tid = threadIdx.x;
    for (int i = tid; i < HD * NEXP; i += 256) {
        int h = i >> 4, e = i & 15;
        sgw[h * 17 + e] = gw[i];
    }
    if (tid < NEXP) sgb[tid] = gb[tid];
    __syncthreads();

    const int warp = tid >> 5, lane = tid & 31;
    for (int tt = 0; tt < 4; tt++) {
        int t = blockIdx.x * 32 + warp * 4 + tt;
        const float4* xr4 = (const float4*)(g_x + (long)t * HD);
        float acc[NEXP];
#pragma unroll
        for (int e = 0; e < NEXP; e++) acc[e] = 0.f;
        for (int i = lane; i < 256; i += 32) {
            float4 xv = xr4[i];
            int h = i << 2;
            const float* s0 = &sgw[(h + 0) * 17];
            const float* s1 = &sgw[(h + 1) * 17];
            const float* s2 = &sgw[(h + 2) * 17];
            const float* s3 = &sgw[(h + 3) * 17];
#pragma unroll
            for (int e = 0; e < NEXP; e++)
                acc[e] = fmaf(xv.x, s0[e], fmaf(xv.y, s1[e],
                         fmaf(xv.z, s2[e], fmaf(xv.w, s3[e], acc[e]))));
        }
#pragma unroll
        for (int e = 0; e < NEXP; e++) {
#pragma unroll
            for (int o = 16; o > 0; o >>= 1)
                acc[e] += __shfl_xor_sync(0xffffffffu, acc[e], o);
        }
        if (lane == 0) {
            float mx = acc[0] + sgb[0];
            float lg[NEXP];
#pragma unroll
            for (int e = 0; e < NEXP; e++) { lg[e] = acc[e] + sgb[e]; mx = fmaxf(mx, lg[e]); }
            float p[NEXP]; float sum = 0.f;
#pragma unroll
            for (int e = 0; e < NEXP; e++) { p[e] = expf(lg[e] - mx); sum += p[e]; }
            float inv = 1.f / sum;
            int i0 = 0; float v0 = -1.f;
#pragma unroll
            for (int e = 0; e < NEXP; e++) if (p[e] > v0) { v0 = p[e]; i0 = e; }
            int i1 = 0; float v1 = -1.f;
#pragma unroll
            for (int e = 0; e < NEXP; e++) if (e != i0 && p[e] > v1) { v1 = p[e]; i1 = e; }
            g_tidx[2 * t]     = i0; g_tval[2 * t]     = v0 * inv;
            g_tidx[2 * t + 1] = i1; g_tval[2 * t + 1] = v1 * inv;
            atomicAdd(&g_cnt[i0], 1);
            atomicAdd(&g_cnt[i1], 1);
        }
    }
}

__global__ void prefix_kernel() {
    if (threadIdx.x == 0 && blockIdx.x == 0) {
        int off = 0;
        for (int e = 0; e < NEXP; e++) {
            g_off[e] = off;
            int tiles = (g_cnt[e] + 63) >> 6;
            for (int tt = 0; tt < tiles; tt++) g_tile_expert[(off >> 6) + tt] = e;
            off += tiles << 6;
        }
        g_off[NEXP] = off;
    }
}

__global__ void scatter_kernel() {
    int t = blockIdx.x * blockDim.x + threadIdx.x;
    if (t >= TOK2) return;
    for (int k = 0; k < 2; k++) {
        int e = g_tidx[2 * t + k];
        int pos = atomicAdd(&g_run[e], 1);
        int slot = g_off[e] + pos;
        g_slot_token[slot] = t;
        g_slot_val[slot]   = g_tval[2 * t + k];
        g_slot_of[2 * t + k] = slot;
    }
}

// ===========================================================================
// tf32 tensor-core GEMM (64x128 tile, 256 threads, cp.async double buffer)
// ===========================================================================
#define AS_STRIDE 20
#define BS_STRIDE 136

__global__ __launch_bounds__(256) void gemm_tc(
    const float* __restrict__ A, int lda, int K,
    const float* __restrict__ W, long estride,
    const float* __restrict__ bias, int bstride,
    float* __restrict__ out,
    const int*   __restrict__ slot_token,
    const float* __restrict__ slot_val,
    const int*   __restrict__ tile_expert,
    int do_gelu, int use_val)
{
    int e = tile_expert ? tile_expert[blockIdx.x] : 0;
    if (e < 0) return;
    const int m0 = blockIdx.x * 64;
    const int n0 = blockIdx.y * 128;
    const float* We = W + (long)e * estride + n0;
    const float* be = bias + (long)e * bstride + n0;

    __shared__ float As[2][64 * AS_STRIDE];
    __shared__ float Bs[2][16 * BS_STRIDE];

    const int tid  = threadIdx.x;
    const int warp = tid >> 5, lane = tid & 31;
    const int wm = warp >> 2;
    const int wn = warp & 3;
    const int gid = lane >> 2;
    const int qid = lane & 3;

    const int a_row = tid >> 2;
    const int a_kq  = (tid & 3) << 2;
    long arow;
    {
        int tok = slot_token ? slot_token[m0 + a_row] : (m0 + a_row);
        if (tok < 0) tok = 0;
        arow = (long)tok * lda;
    }

    float c[2][4][4];
#pragma unroll
    for (int mt = 0; mt < 2; mt++)
#pragma unroll
        for (int nt = 0; nt < 4; nt++)
#pragma unroll
            for (int r = 0; r < 4; r++) c[mt][nt][r] = 0.f;

    const int NKC = K >> 4;

#define ISSUE_STAGE(K0, S)                                                        \
    {                                                                             \
        uint32_t da = (uint32_t)__cvta_generic_to_shared(                         \
            &As[S][a_row * AS_STRIDE + a_kq]);                                    \
        asm volatile("cp.async.cg.shared.global [%0], [%1], 16;" ::               \
                     "r"(da), "l"(A + arow + (K0) + a_kq));                       \
        _Pragma("unroll")                                                         \
        for (int j = 0; j < 2; j++) {                                             \
            int ch = tid + j * 256;                                               \
            int krow = ch >> 5, nq = (ch & 31) << 2;                              \
            uint32_t db = (uint32_t)__cvta_generic_to_shared(                     \
                &Bs[S][krow * BS_STRIDE + nq]);                                   \
            asm volatile("cp.async.cg.shared.global [%0], [%1], 16;" ::           \
                         "r"(db), "l"(We + (long)((K0) + krow) * 1024 + nq));     \
        }                                                                         \
        asm volatile("cp.async.commit_group;");                                   \
    }

    ISSUE_STAGE(0, 0);
    int s = 0;
    for (int kc = 0; kc < NKC; kc++) {
        if (kc + 1 < NKC) {
            ISSUE_STAGE((kc + 1) << 4, s ^ 1);
            asm volatile("cp.async.wait_group 1;");
        } else {
            asm volatile("cp.async.wait_group 0;");
        }
        __syncthreads();

#pragma unroll
        for (int kb = 0; kb < 2; kb++) {
            uint32_t af[2][4], bf[4][2];
            const float* ap = &As[s][0];
            const float* bp = &Bs[s][0];
#pragma unroll
            for (int mt = 0; mt < 2; mt++) {
                int r = wm * 32 + mt * 16 + gid;
                af[mt][0] = cvt_tf32(ap[(r)     * AS_STRIDE + kb * 8 + qid]);
                af[mt][1] = cvt_tf32(ap[(r + 8) * AS_STRIDE + kb * 8 + qid]);
                af[mt][2] = cvt_tf32(ap[(r)     * AS_STRIDE + kb * 8 + qid + 4]);
                af[mt][3] = cvt_tf32(ap[(r + 8) * AS_STRIDE + kb * 8 + qid + 4]);
            }
#pragma unroll
            for (int nt = 0; nt < 4; nt++) {
                int n = wn * 32 + nt * 8 + gid;
                bf[nt][0] = cvt_tf32(bp[(kb * 8 + qid)     * BS_STRIDE + n]);
                bf[nt][1] = cvt_tf32(bp[(kb * 8 + qid + 4) * BS_STRIDE + n]);
            }
#pragma unroll
            for (int mt = 0; mt < 2; mt++)
#pragma unroll
                for (int nt = 0; nt < 4; nt++)
                    mma_tf32(c[mt][nt], af[mt], bf[nt]);
        }
        __syncthreads();
        s ^= 1;
    }

#pragma unroll
    for (int mt = 0; mt < 2; mt++) {
        int rbase = m0 + wm * 32 + mt * 16 + gid;
#pragma unroll
        for (int half = 0; half < 2; half++) {
            int r = rbase + half * 8;
            float sv = use_val ? slot_val[r] : 1.f;
#pragma unroll
            for (int nt = 0; nt < 4; nt++) {
                int colb = wn * 32 + nt * 8 + qid * 2;
                float v0 = c[mt][nt][half * 2 + 0] + be[colb];
                float v1 = c[mt][nt][half * 2 + 1] + be[colb + 1];
                if (do_gelu) { v0 = gelu_f(v0); v1 = gelu_f(v1); }
                if (use_val) { v0 *= sv; v1 *= sv; }
                *(float2*)(out + (long)r * 1024 + n0 + colb) = make_float2(v0, v1);
            }
        }
    }
#undef ISSUE_STAGE
}

// ---- combine 2 expert outputs + LN + gelu, fused cat-LN stat accumulation --
__global__ __launch_bounds__(256) void moe_combine_ln(
    const float* __restrict__ g0, const float* __restrict__ b0,
    const float* __restrict__ g1, const float* __restrict__ b1,
    float* __restrict__ dout)
{
    int t = blockIdx.x;
    const float4* r0 = (const float4*)(g_eo + (long)g_slot_of[2 * t] * HD);
    const float4* r1 = (const float4*)(g_eo + (long)g_slot_of[2 * t + 1] * HD);
    const float4* G  = (const float4*)((t < TOK) ? g0 : g1);
    const float4* Bv = (const float4*)((t < TOK) ? b0 : b1);
    float s = 0.f, ss = 0.f;
    {
        int i = threadIdx.x;
        float4 a = r0[i], b = r1[i];
        float vx = a.x + b.x, vy = a.y + b.y, vz = a.z + b.z, vw = a.w + b.w;
        s += vx + vy + vz + vw;
        ss = fmaf(vx, vx, fmaf(vy, vy, fmaf(vz, vz, fmaf(vw, vw, ss))));
    }
    __shared__ float sh1[256], sh2[256];
    sh1[threadIdx.x] = s; sh2[threadIdx.x] = ss;
    __syncthreads();
    for (int o = 128; o > 0; o >>= 1) {
        if (threadIdx.x < o) { sh1[threadIdx.x] += sh1[threadIdx.x + o];
                               sh2[threadIdx.x] += sh2[threadIdx.x + o]; }
        __syncthreads();
    }
    float mean = sh1[0] / HD;
    float rstd = rsqrtf(sh2[0] / HD - mean * mean + 1e-5f);
    float4* orow = (float4*)(dout + OFF_R + (long)t * HD);
    float os, oss;
    {
        int i = threadIdx.x;
        float4 a = r0[i], b = r1[i], gg = G[i], bb = Bv[i];
        float4 r;
        r.x = gelu_f(((a.x + b.x) - mean) * rstd * gg.x + bb.x);
        r.y = gelu_f(((a.y + b.y) - mean) * rstd * gg.y + bb.y);
        r.z = gelu_f(((a.z + b.z) - mean) * rstd * gg.z + bb.z);
        r.w = gelu_f(((a.w + b.w) - mean) * rstd * gg.w + bb.w);
        orow[i] = r;
        os  = r.x + r.y + r.z + r.w;
        oss = fmaf(r.x, r.x, fmaf(r.y, r.y, fmaf(r.z, r.z, r.w * r.w)));
    }
    __syncthreads();
    sh1[threadIdx.x] = os; sh2[threadIdx.x] = oss;
    __syncthreads();
    for (int o = 128; o > 0; o >>= 1) {
        if (threadIdx.x < o) { sh1[threadIdx.x] += sh1[threadIdx.x + o];
                               sh2[threadIdx.x] += sh2[threadIdx.x + o]; }
        __syncthreads();
    }
    if (threadIdx.x == 0) {
        int tt = (t < TOK) ? t : t - TOK;
        atomicAdd(&g_cmu[tt], sh1[0]);
        atomicAdd(&g_crs[tt], sh2[0]);
    }
}

// -------- finalize cat-LN stats: sums -> mean/rstd --------------------------
__global__ void cat_mu_kernel() {
    int t = blockIdx.x * blockDim.x + threadIdx.x;
    if (t >= TOK) return;
    float mean = g_cmu[t] / 2048.f;
    float rs = rsqrtf(g_crs[t] / 2048.f - mean * mean + 1e-5f);
    g_cmu[t] = mean;
    g_crs[t] = rs;
}

// -------- cat-LN apply + transpose into g_c[b][f][s] ------------------------
__global__ __launch_bounds__(256) void cat_tr_kernel(
    const float* __restrict__ dout,
    const float* __restrict__ g2, const float* __restrict__ b2)
{
    __shared__ float sT[64 * 52];
    const int b  = blockIdx.x;
    const int f0 = blockIdx.y * 64;
    const int tid = threadIdx.x;
    for (int i = tid; i < 3200; i += 256) {
        int s2 = i >> 6, fl = i & 63;
        int f = f0 + fl, t = b * 50 + s2;
        float v = (f < HD) ? dout[OFF_R + (long)t * HD + f]
                           : dout[OFF_R + (long)(TOK + t) * HD + (f - HD)];
        v = (v - g_cmu[t]) * g_crs[t] * g2[f] + b2[f];
        sT[fl * 52 + s2] = gelu_f(v);
    }
    __syncthreads();
    for (int i = tid; i < 3200; i += 256) {
        int fl = i / 50, s2 = i % 50;
        g_c[((long)b * 2048 + f0 + fl) * 50 + s2] = sT[fl * 52 + s2];
    }
}

// ===========================================================================
// Fused attention layer, 320 threads; 4x5 tiles (R14); __expf softmax.
// ===========================================================================
#define ATT_OX 0
#define ATT_OQ 3328
#define ATT_OA 13056
#define ATT_OW 16384
#define ATT_OB 24184
#define ATT_SMEM_FLOATS 24448
#define ATT_THREADS 320

__global__ __launch_bounds__(ATT_THREADS, 1) void attn_layer_fused(
    const float* __restrict__ wi, const float* __restrict__ bi,
    const float* __restrict__ wo, const float* __restrict__ bo,
    const float* __restrict__ wp, const float* __restrict__ bp)
{
    extern __shared__ float sm[];
    float* sX  = sm + ATT_OX;    // [64][52]
    float* sQ  = sm + ATT_OQ;    // [64][152] qkv; later reused as sM [64][52]
    float* sA  = sm + ATT_OA;    // [64][52]
    float* sW  = sm + ATT_OW;    // [150][52]
    float* sbi = sm + ATT_OB;    // [150]
    float* sbo = sbi + 150;      // [50]
    float* sbp = sbo + 50;       // [50]

    const int n = blockIdx.x;
    const int tid = threadIdx.x;

    // phase 1: load x rows + wi + bi
    for (int i = tid; i < 3200; i += ATT_THREADS) {
        int m = i / 50, k = i % 50;
        sX[m * 52 + k] = g_c[((long)m * 2048 + n) * 50 + k];
    }
    for (int i = tid; i < 7500; i += ATT_THREADS)
        sW[(i / 50) * 52 + (i % 50)] = wi[i];
    if (tid < 150) sbi[tid] = bi[tid];
    __syncthreads();

    // phase 2: qkv = x @ wi^T + bi (480 tiles of 4x5)
    for (int t = tid; t < 480; t += ATT_THREADS) {
        int tm = (t / 30) * 4, tf = (t % 30) * 5;
        float acc[4][5];
#pragma unroll
        for (int i = 0; i < 4; i++)
#pragma unroll
            for (int j = 0; j < 5; j++) acc[i][j] = sbi[tf + j];
#pragma unroll 5
        for (int k = 0; k < 50; k++) {
            float a0 = sX[(tm)     * 52 + k], a1 = sX[(tm + 1) * 52 + k];
            float a2 = sX[(tm + 2) * 52 + k], a3 = sX[(tm + 3) * 52 + k];
#pragma unroll
            for (int j = 0; j < 5; j++) {
                float w = sW[(tf + j) * 52 + k];
                acc[0][j] = fmaf(a0, w, acc[0][j]);
                acc[1][j] = fmaf(a1, w, acc[1][j]);
                acc[2][j] = fmaf(a2, w, acc[2][j]);
                acc[3][j] = fmaf(a3, w, acc[3][j]);
            }
        }
#pragma unroll
        for (int i = 0; i < 4; i++)
#pragma unroll
            for (int j = 0; j < 5; j++)
                sQ[(tm + i) * 152 + tf + j] = acc[i][j];
    }
    __syncthreads();

    // phase 3: attention, one task per thread (320 = 64 l x 5 h)
    {
        const float scale = 0.31622776601683794f;
        int l = tid & 63, h = tid >> 6;
        const float* qp = &sQ[l * 152 + h * 10];
        float q[10];
#pragma unroll
        for (int d = 0; d < 10; d++) q[d] = qp[d];
        float sc[64];
        float mx = -1e30f;
#pragma unroll
        for (int m = 0; m < 64; m++) {
            const float* kp = &sQ[m * 152 + 50 + h * 10];
            float s = 0.f;
#pragma unroll
            for (int d = 0; d < 10; d++) s = fmaf(q[d], kp[d], s);
            s *= scale;
            sc[m] = s;
            mx = fmaxf(mx, s);
        }
        float sum = 0.f;
#pragma unroll
        for (int m = 0; m < 64; m++) { sc[m] = __expf(sc[m] - mx); sum += sc[m]; }
        float o[10];
#pragma unroll
        for (int d = 0; d < 10; d++) o[d] = 0.f;
#pragma unroll
        for (int m = 0; m < 64; m++) {
            const float* vp = &sQ[m * 152 + 100 + h * 10];
            float ev = sc[m];
#pragma unroll
            for (int d = 0; d < 10; d++) o[d] = fmaf(ev, vp[d], o[d]);
        }
        float inv = 1.f / sum;
        float* ap = &sA[l * 52 + h * 10];
#pragma unroll
        for (int d = 0; d < 10; d++) ap[d] = o[d] * inv;
    }
    for (int i = tid; i < 2500; i += ATT_THREADS)
        sW[(i / 50) * 52 + (i % 50)] = wo[i];
    for (int i = tid; i < 2500; i += ATT_THREADS)
        sW[(50 + i / 50) * 52 + (i % 50)] = wp[i];
    if (tid < 50) { sbo[tid] = bo[tid]; sbp[tid] = bp[tid]; }
    __syncthreads();

    // phase 4: sM = gelu(att @ wo^T + bo) -> sQ ([64][52]); 160 tasks of 4x5
    for (int t = tid; t < 160; t += ATT_THREADS) {
        int tm = (t / 10) * 4, tf = (t % 10) * 5;
        float acc[4][5];
#pragma unroll
        for (int i = 0; i < 4; i++)
#pragma unroll
            for (int j = 0; j < 5; j++) acc[i][j] = sbo[tf + j];
#pragma unroll 5
        for (int k = 0; k < 50; k++) {
            float a0 = sA[(tm)     * 52 + k], a1 = sA[(tm + 1) * 52 + k];
            float a2 = sA[(tm + 2) * 52 + k], a3 = sA[(tm + 3) * 52 + k];
#pragma unroll
            for (int j = 0; j < 5; j++) {
                float w = sW[(tf + j) * 52 + k];
                acc[0][j] = fmaf(a0, w, acc[0][j]);
                acc[1][j] = fmaf(a1, w, acc[1][j]);
                acc[2][j] = fmaf(a2, w, acc[2][j]);
                acc[3][j] = fmaf(a3, w, acc[3][j]);
            }
        }
#pragma unroll
        for (int i = 0; i < 4; i++)
#pragma unroll
            for (int j = 0; j < 5; j++)
                sQ[(tm + i) * 52 + tf + j] = gelu_f(acc[i][j]);
    }
    __syncthreads();

    // phase 5: c = x + gelu(sM @ wp^T + bp); 160 tasks of 4x5
    for (int t = tid; t < 160; t += ATT_THREADS) {
        int tm = (t / 10) * 4, tf = (t % 10) * 5;
        float acc[4][5];
#pragma unroll
        for (int i = 0; i < 4; i++)
#pragma unroll
            for (int j = 0; j < 5; j++) acc[i][j] = sbp[tf + j];
#pragma unroll 5
        for (int k = 0; k < 50; k++) {
            float a0 = sQ[(tm)     * 52 + k], a1 = sQ[(tm + 1) * 52 + k];
            float a2 = sQ[(tm + 2) * 52 + k], a3 = sQ[(tm + 3) * 52 + k];
#pragma unroll
            for (int j = 0; j < 5; j++) {
                float w = sW[(50 + tf + j) * 52 + k];
                acc[0][j] = fmaf(a0, w, acc[0][j]);
                acc[1][j] = fmaf(a1, w, acc[1][j]);
                acc[2][j] = fmaf(a2, w, acc[2][j]);
                acc[3][j] = fmaf(a3, w, acc[3][j]);
            }
        }
#pragma unroll
        for (int i = 0; i < 4; i++)
#pragma unroll
            for (int j = 0; j < 5; j++) {
                int m = tm + i, f = tf + j;
                g_c[((long)m * 2048 + n) * 50 + f] =
                    sX[m * 52 + f] + gelu_f(acc[i][j]);
            }
    }
}

// -------- back-LN stats ------------------------------------------------------
__global__ __launch_bounds__(256) void back_stats_kernel()
{
    __shared__ float sT[64 * 52];
    const int b  = blockIdx.x;
    const int f0 = blockIdx.y * 64;
    const int tid = threadIdx.x;
    for (int i = tid; i < 3200; i += 256) {
        int fl = i / 50, s2 = i % 50;
        sT[fl * 52 + s2] = g_c[((long)b * 2048 + f0 + fl) * 50 + s2];
    }
    __syncthreads();
    if (tid < 200) {
        int s2 = tid % 50, part = tid / 50;
        float s = 0.f, ss = 0.f;
        for (int fl = part * 16; fl < part * 16 + 16; fl++) {
            float v = sT[fl * 52 + s2];
            s += v; ss = fmaf(v, v, ss);
        }
        atomicAdd(&g_bsum[b * 50 + s2], s);
        atomicAdd(&g_bss [b * 50 + s2], ss);
    }
}

__global__ void back_mu_kernel() {
    int t = blockIdx.x * blockDim.x + threadIdx.x;
    if (t >= TOK) return;
    float mean = g_bsum[t] / 2048.f;
    float rs = rsqrtf(g_bss[t] / 2048.f - mean * mean + 1e-5f);
    g_bsum[t] = mean;
    g_bss[t]  = rs;
}

// -------- back-LN apply + transpose into g_c2 -------------------------------
__global__ __launch_bounds__(256) void back_tr_kernel(
    const float* __restrict__ aag, const float* __restrict__ aab)
{
    __shared__ float sT[64 * 52];
    const int b  = blockIdx.x;
    const int f0 = blockIdx.y * 64;
    const int tid = threadIdx.x;
    for (int i = tid; i < 3200; i += 256) {
        int fl = i / 50, s2 = i % 50;
        sT[fl * 52 + s2] = g_c[((long)b * 2048 + f0 + fl) * 50 + s2];
    }
    __syncthreads();
    for (int i = tid; i < 3200; i += 256) {
        int s2 = i >> 6, fl = i & 63;
        int t = b * 50 + s2, f = f0 + fl;
        float v = (sT[fl * 52 + s2] - g_bsum[t]) * g_bss[t] * aag[f] + aab[f];
        g_c2[(long)t * 2048 + f] = gelu_f(v);
    }
}

// ---------------- mean over S -> result ----------------
__global__ __launch_bounds__(256) void mean_kernel(float* __restrict__ dout)
{
    int bb = blockIdx.x;
    for (int hh = threadIdx.x; hh < HD; hh += 256) {
        float s = 0.f;
        for (int s2 = 0; s2 < 50; s2++)
            s += g_fo2[((long)bb * 50 + s2) * HD + hh];
        dout[bb * HD + hh] = s * (1.0f / 50.0f);
    }
}

// ---------------------------------------------------------------------------
extern "C" void kernel_launch(void* const* d_in, const int* in_sizes, int n_in,
                              void* d_out, int out_size)
{
    const float* cls_x   = (const float*)d_in[0];
    const float* cls_x1  = (const float*)d_in[1];
    const float* ln_g    = (const float*)d_in[2];
    const float* ln_b    = (const float*)d_in[3];
    const float* ln1_g   = (const float*)d_in[4];
    const float* ln1_b   = (const float*)d_in[5];
    const float* gate_w  = (const float*)d_in[6];
    const float* gate_b  = (const float*)d_in[7];
    const float* W1      = (const float*)d_in[8];
    const float* b1      = (const float*)d_in[9];
    const float* W2      = (const float*)d_in[10];
    const float* b2      = (const float*)d_in[11];
    const float* lnout_g = (const float*)d_in[12];
    const float* lnout_b = (const float*)d_in[13];
    const float* lnout1_g= (const float*)d_in[14];
    const float* lnout1_b= (const float*)d_in[15];
    const float* ln2_g   = (const float*)d_in[16];
    const float* ln2_b   = (const float*)d_in[17];
    const float* attn_in_w  = (const float*)d_in[18];
    const float* attn_in_b  = (const float*)d_in[19];
    const float* attn_out_w = (const float*)d_in[20];
    const float* attn_out_b = (const float*)d_in[21];
    const float* post_w  = (const float*)d_in[22];
    const float* post_b  = (const float*)d_in[23];
    const float* aa_g    = (const float*)d_in[24];
    const float* aa_b    = (const float*)d_in[25];
    const float* fus_w   = (const float*)d_in[26];
    const float* fus_b   = (const float*)d_in[27];
    const float* ln3_g   = (const float*)d_in[28];
    const float* ln3_b   = (const float*)d_in[29];
    float* out = (float*)d_out;

    float *p_x, *p_h, *p_eo, *p_c2, *p_fo, *p_fo2;
    int *p_slot_token, *p_tile_expert; float *p_slot_val;
    cudaGetSymbolAddress((void**)&p_x,   g_x);
    cudaGetSymbolAddress((void**)&p_h,   g_h);
    cudaGetSymbolAddress((void**)&p_eo,  g_eo);
    cudaGetSymbolAddress((void**)&p_c2,  g_c2);
    cudaGetSymbolAddress((void**)&p_fo,  g_fo);
    cudaGetSymbolAddress((void**)&p_fo2, g_fo2);
    cudaGetSymbolAddress((void**)&p_slot_token,  g_slot_token);
    cudaGetSymbolAddress((void**)&p_slot_val,    g_slot_val);
    cudaGetSymbolAddress((void**)&p_tile_expert, g_tile_expert);

    const int SGW_BYTES = HD * 17 * 4;                 // 69632
    const int ATT_BYTES = ATT_SMEM_FLOATS * 4;         // 97792
    cudaFuncSetAttribute(gate_topk2, cudaFuncAttributeMaxDynamicSharedMemorySize,
                         SGW_BYTES);
    cudaFuncSetAttribute(attn_layer_fused, cudaFuncAttributeMaxDynamicSharedMemorySize,
                         ATT_BYTES);

    // Stage A
    ln_gelu_kernel<<<TOK, 256>>>(cls_x,  ln_g,  ln_b,  p_x,             HD);
    ln_gelu_kernel<<<TOK, 256>>>(cls_x1, ln1_g, ln1_b, p_x + TOK * HD,  HD);

    // Stage B
    init_routing<<<54, 256>>>();
    gate_topk2<<<TOK2 / 32, 256, SGW_BYTES>>>(gate_w, gate_b);
    prefix_kernel<<<1, 32>>>();
    scatter_kernel<<<(TOK2 + 255) / 256, 256>>>();

    // Stage C
    gemm_tc<<<dim3(NTILE, 8), 256>>>(p_x, HD, HD, W1, 1024L * 1024, b1, 1024,
                                     p_h, p_slot_token, nullptr, p_tile_expert, 1, 0);
    gemm_tc<<<dim3(NTILE, 8), 256>>>(p_h, HD, HD, W2, 1024L * 1024, b2, 1024,
                                     p_eo, nullptr, p_slot_val, p_tile_expert, 1, 1);

    // Stage D (also accumulates cat-LN stats)
    moe_combine_ln<<<TOK2, 256>>>(lnout_g, lnout_b, lnout1_g, lnout1_b, out);

    // Stage E
    cat_mu_kernel<<<(TOK + 255) / 256, 256>>>();
    cat_tr_kernel<<<dim3(64, 32), 256>>>(out, ln2_g, ln2_b);

    // Stage F
    for (int i = 0; i < 4; i++) {
        attn_layer_fused<<<2048, ATT_THREADS, ATT_BYTES>>>(
            attn_in_w + i * 7500, attn_in_b + i * 150,
            attn_out_w + i * 2500, attn_out_b + i * 50,
            post_w + i * 2500, post_b + i * 50);
    }

    // Stage G
    back_stats_kernel<<<dim3(64, 32), 256>>>();
    back_mu_kernel<<<(TOK + 255) / 256, 256>>>();
    back_tr_kernel<<<dim3(64, 32), 256>>>(aa_g, aa_b);

    // Stage H
    gemm_tc<<<dim3(TOK / 64, 8), 256>>>(p_c2, 2048, 2048, fus_w, 0, fus_b, 0,
                                        p_fo, nullptr, nullptr, nullptr, 0, 0);

    // Stage I
    ln_gelu_kernel<<<TOK, 256>>>(p_fo, ln3_g, ln3_b, p_fo2, HD);
    mean_kernel<<<64, 256>>>(out);
}